// round 2
// baseline (speedup 1.0000x reference)
#include <cuda_runtime.h>
#include <cstdint>

#define IN_F   4096
#define OUT_F  4096
#define M_ROWS 512

// 64 MB scratch for dequantized (tf32-rounded) weights, row-major [OUT_F][IN_F]
__device__ float g_W[(size_t)OUT_F * IN_F];

__device__ __forceinline__ float to_tf32(float x) {
    uint32_t u;
    asm("cvt.rna.tf32.f32 %0, %1;" : "=r"(u) : "f"(x));
    return __uint_as_float(u);
}

// ---------------------------------------------------------------------------
// Kernel 1: dequant + outlier correction -> g_W (tf32-rounded fp32 values)
// ---------------------------------------------------------------------------
__global__ void dequant_kernel(const int* __restrict__ q,
                               const float* __restrict__ scales,
                               const float* __restrict__ zeros,
                               const float* __restrict__ outlier,
                               const float* __restrict__ grad) {
    size_t i = (size_t)blockIdx.x * blockDim.x + threadIdx.x;
    size_t base = i * 4;
    if (base >= (size_t)OUT_F * IN_F) return;
    int row = (int)(base >> 12);  // IN_F = 4096
    float s = scales[row];
    float z = zeros[row];
    int4   qv = *reinterpret_cast<const int4*>(q + base);
    float4 ov = *reinterpret_cast<const float4*>(outlier + base);
    float4 gv = *reinterpret_cast<const float4*>(grad + base);
    float4 w;
    w.x = to_tf32(((float)qv.x - z) * s + ov.x * gv.x);
    w.y = to_tf32(((float)qv.y - z) * s + ov.y * gv.y);
    w.z = to_tf32(((float)qv.z - z) * s + ov.z * gv.z);
    w.w = to_tf32(((float)qv.w - z) * s + ov.w * gv.w);
    *reinterpret_cast<float4*>(g_W + base) = w;
}

// ---------------------------------------------------------------------------
// Kernel 2: Y = X @ W^T + b via mma.sync tf32 m16n8k8
// CTA tile 128x128, BK=32, 256 threads (8 warps in 2x4), warp tile 64x32.
// ---------------------------------------------------------------------------
#define BM 128
#define BN 128
#define BK 32
#define LDA 36  // BK + 4 pad (conflict-free fragment loads)

__device__ __forceinline__ void mma_tf32(float c[4],
                                         const float a[4],
                                         const float b[2]) {
    asm volatile(
        "mma.sync.aligned.m16n8k8.row.col.f32.tf32.tf32.f32 "
        "{%0,%1,%2,%3}, {%4,%5,%6,%7}, {%8,%9}, {%0,%1,%2,%3};"
        : "+f"(c[0]), "+f"(c[1]), "+f"(c[2]), "+f"(c[3])
        : "r"(__float_as_uint(a[0])), "r"(__float_as_uint(a[1])),
          "r"(__float_as_uint(a[2])), "r"(__float_as_uint(a[3])),
          "r"(__float_as_uint(b[0])), "r"(__float_as_uint(b[1])));
}

__global__ __launch_bounds__(256, 1)
void gemm_kernel(const float* __restrict__ A,
                 const float* __restrict__ bias,
                 float* __restrict__ out) {
    __shared__ __align__(16) float As[BM * LDA];
    __shared__ __align__(16) float Bs[BN * LDA];

    const int tid = threadIdx.x;
    const int bm  = blockIdx.x;   // 0..3 (fastest -> co-resident CTAs share W in L2)
    const int bn  = blockIdx.y;   // 0..31

    const float* Ag = A   + (size_t)(bm * BM) * IN_F;
    const float* Wg = g_W + (size_t)(bn * BN) * IN_F;

    const int lrow = tid >> 3;        // 0..31
    const int lvec = (tid & 7) * 4;   // 0,4,...,28

    const int warp = tid >> 5;
    const int lane = tid & 31;
    const int wm = warp & 1;          // 2 warps along M
    const int wn = warp >> 1;         // 4 warps along N
    const int m_base = wm * 64;
    const int n_base = wn * 32;
    const int gid = lane >> 2;        // 0..7
    const int tig = lane & 3;         // 0..3

    float4 ar[4], br[4];
    float  c[4][4][4];
    #pragma unroll
    for (int mi = 0; mi < 4; mi++)
        #pragma unroll
        for (int ni = 0; ni < 4; ni++)
            #pragma unroll
            for (int r = 0; r < 4; r++) c[mi][ni][r] = 0.0f;

    auto ldg_tile = [&](int k0) {
        #pragma unroll
        for (int r = 0; r < 4; r++) {
            int row = lrow + r * 32;
            ar[r] = *reinterpret_cast<const float4*>(Ag + (size_t)row * IN_F + k0 + lvec);
            br[r] = *reinterpret_cast<const float4*>(Wg + (size_t)row * IN_F + k0 + lvec);
        }
    };

    ldg_tile(0);

    const int KT = IN_F / BK;  // 128
    for (int kt = 0; kt < KT; kt++) {
        __syncthreads();  // prior compute done; safe to overwrite smem
        #pragma unroll
        for (int r = 0; r < 4; r++) {
            int row = lrow + r * 32;
            float4 a4 = ar[r];
            a4.x = to_tf32(a4.x); a4.y = to_tf32(a4.y);
            a4.z = to_tf32(a4.z); a4.w = to_tf32(a4.w);
            *reinterpret_cast<float4*>(&As[row * LDA + lvec]) = a4;
            *reinterpret_cast<float4*>(&Bs[row * LDA + lvec]) = br[r];  // already tf32-valued
        }
        __syncthreads();

        if (kt + 1 < KT) ldg_tile((kt + 1) * BK);  // overlap LDG with compute

        #pragma unroll
        for (int kk = 0; kk < 4; kk++) {
            const int k8 = kk * 8;
            float a[4][4];
            #pragma unroll
            for (int mi = 0; mi < 4; mi++) {
                int r0 = m_base + mi * 16 + gid;
                a[mi][0] = As[(r0)     * LDA + k8 + tig];
                a[mi][1] = As[(r0 + 8) * LDA + k8 + tig];
                a[mi][2] = As[(r0)     * LDA + k8 + tig + 4];
                a[mi][3] = As[(r0 + 8) * LDA + k8 + tig + 4];
            }
            float b[4][2];
            #pragma unroll
            for (int ni = 0; ni < 4; ni++) {
                int cN = n_base + ni * 8 + gid;
                b[ni][0] = Bs[cN * LDA + k8 + tig];
                b[ni][1] = Bs[cN * LDA + k8 + tig + 4];
            }
            #pragma unroll
            for (int mi = 0; mi < 4; mi++)
                #pragma unroll
                for (int ni = 0; ni < 4; ni++)
                    mma_tf32(c[mi][ni], a[mi], b[ni]);
        }
    }

    // Epilogue: += bias, store fp32
    #pragma unroll
    for (int mi = 0; mi < 4; mi++) {
        int row0 = bm * BM + m_base + mi * 16 + gid;
        #pragma unroll
        for (int ni = 0; ni < 4; ni++) {
            int col = bn * BN + n_base + ni * 8 + tig * 2;
            float b0 = bias[col], b1 = bias[col + 1];
            float2 v;
            v.x = c[mi][ni][0] + b0;
            v.y = c[mi][ni][1] + b1;
            *reinterpret_cast<float2*>(out + (size_t)row0 * OUT_F + col) = v;
            v.x = c[mi][ni][2] + b0;
            v.y = c[mi][ni][3] + b1;
            *reinterpret_cast<float2*>(out + (size_t)(row0 + 8) * OUT_F + col) = v;
        }
    }
}

// ---------------------------------------------------------------------------
extern "C" void kernel_launch(void* const* d_in, const int* in_sizes, int n_in,
                              void* d_out, int out_size) {
    const float* input    = (const float*)d_in[0];
    const int*   qweight  = (const int*)  d_in[1];
    const float* scales   = (const float*)d_in[2];
    const float* zeros    = (const float*)d_in[3];
    const float* outlier  = (const float*)d_in[4];
    const float* grad     = (const float*)d_in[5];
    const float* bias     = (const float*)d_in[6];
    float*       out      = (float*)d_out;

    // Pass 1: dequant 16.7M elements, 4 per thread
    int total_vec4 = (OUT_F * IN_F) / 4;
    dequant_kernel<<<total_vec4 / 256, 256>>>(qweight, scales, zeros, outlier, grad);

    // Pass 2: GEMM. grid.x = M tiles (fastest) so CTAs sharing W are co-resident.
    dim3 grid(M_ROWS / BM, OUT_F / BN);
    gemm_kernel<<<grid, 256>>>(input, bias, out);
}

// round 5
// speedup vs baseline: 1.8759x; 1.8759x over previous
#include <cuda_runtime.h>
#include <cuda_fp16.h>
#include <cstdint>

#define IN_F   4096
#define OUT_F  4096
#define M_ROWS 512

#define BM 128
#define BN 128
#define BK 64                  // fp16 elems -> 128B rows (XOR-swizzle atom)
#define KT (IN_F / BK)         // 64
#define STAGES 4
#define TILE_B  (BM * BK * 2)  // 16384 B per operand
#define STAGE_B (2 * TILE_B)   // 32 KB
#define SMEM_SIZE (STAGES * STAGE_B)  // 128 KB

// fp16 scratch: dequantized W [OUT_F][IN_F], converted X [M_ROWS][IN_F]
__device__ __half g_W[(size_t)OUT_F * IN_F];
__device__ __half g_X[(size_t)M_ROWS * IN_F];

// ---------------------------------------------------------------- helpers
__device__ __forceinline__ uint32_t s2u(const void* p) {
    uint32_t a;
    asm("{ .reg .u64 t; cvta.to.shared.u64 t, %1; cvt.u32.u64 %0, t; }" : "=r"(a) : "l"(p));
    return a;
}
__device__ __forceinline__ uint32_t swz(uint32_t b) { return b ^ ((b >> 3) & 0x70); }

__device__ __forceinline__ void cp_async16(uint32_t dst, const void* src) {
    asm volatile("cp.async.cg.shared.global [%0], [%1], 16;" :: "r"(dst), "l"(src));
}
__device__ __forceinline__ void cp_commit() { asm volatile("cp.async.commit_group;" ::: "memory"); }
template <int N> __device__ __forceinline__ void cp_wait() {
    asm volatile("cp.async.wait_group %0;" :: "n"(N) : "memory");
}

__device__ __forceinline__ void ldmatrix_x4(uint32_t* r, uint32_t addr) {
    asm volatile("ldmatrix.sync.aligned.m8n8.x4.shared.b16 {%0,%1,%2,%3}, [%4];"
                 : "=r"(r[0]), "=r"(r[1]), "=r"(r[2]), "=r"(r[3]) : "r"(addr));
}

__device__ __forceinline__ void mma_f16(float c[4], const uint32_t a[4],
                                        uint32_t b0, uint32_t b1) {
    asm volatile(
        "mma.sync.aligned.m16n8k16.row.col.f32.f16.f16.f32 "
        "{%0,%1,%2,%3}, {%4,%5,%6,%7}, {%8,%9}, {%0,%1,%2,%3};"
        : "+f"(c[0]), "+f"(c[1]), "+f"(c[2]), "+f"(c[3])
        : "r"(a[0]), "r"(a[1]), "r"(a[2]), "r"(a[3]), "r"(b0), "r"(b1));
}

// ---------------------------------------------------------------- pass 1: dequant -> fp16
__global__ void dequant_kernel(const int* __restrict__ q,
                               const float* __restrict__ scales,
                               const float* __restrict__ zeros,
                               const float* __restrict__ outlier,
                               const float* __restrict__ grad) {
    size_t base = ((size_t)blockIdx.x * blockDim.x + threadIdx.x) * 4;
    int row = (int)(base >> 12);  // IN_F = 4096
    float s = scales[row];
    float z = zeros[row];
    int4   qv = *reinterpret_cast<const int4*>(q + base);
    float4 ov = *reinterpret_cast<const float4*>(outlier + base);
    float4 gv = *reinterpret_cast<const float4*>(grad + base);
    float w0 = ((float)qv.x - z) * s + ov.x * gv.x;
    float w1 = ((float)qv.y - z) * s + ov.y * gv.y;
    float w2 = ((float)qv.z - z) * s + ov.z * gv.z;
    float w3 = ((float)qv.w - z) * s + ov.w * gv.w;
    union { __half2 h[2]; uint2 u; } cv;
    cv.h[0] = __floats2half2_rn(w0, w1);
    cv.h[1] = __floats2half2_rn(w2, w3);
    *reinterpret_cast<uint2*>(g_W + base) = cv.u;
}

__global__ void xcvt_kernel(const float* __restrict__ x) {
    size_t base = ((size_t)blockIdx.x * blockDim.x + threadIdx.x) * 4;
    float4 v = *reinterpret_cast<const float4*>(x + base);
    union { __half2 h[2]; uint2 u; } cv;
    cv.h[0] = __floats2half2_rn(v.x, v.y);
    cv.h[1] = __floats2half2_rn(v.z, v.w);
    *reinterpret_cast<uint2*>(g_X + base) = cv.u;
}

// ---------------------------------------------------------------- pass 2: fp16 mma.sync GEMM
// CTA 128x128, 8 warps (2x4), warp tile 64x32, ldmatrix fragments, 4-stage cp.async.
__global__ __launch_bounds__(256, 1)
void gemm_kernel(const float* __restrict__ bias, float* __restrict__ out) {
    extern __shared__ char smem_raw[];
    const uint32_t tiles = s2u(smem_raw);

    const int tid  = threadIdx.x;
    const int warp = tid >> 5;
    const int lane = tid & 31;
    const int bm   = blockIdx.x;  // 0..3 (fastest -> co-resident CTAs share W in L2)
    const int bn   = blockIdx.y;  // 0..31

    const int m_base = (warp & 1) * 64;   // 2 warps along M
    const int n_base = (warp >> 1) * 32;  // 4 warps along N

    const __half* Abase = g_X + (size_t)(bm * BM) * IN_F;
    const __half* Bbase = g_W + (size_t)(bn * BN) * IN_F;

    // per-thread ldmatrix address components (row within 16-row group + k half)
    const int lm_r = lane & 15;        // row within 16
    const int lm_h = (lane >> 4) * 16; // 0 or 16 bytes (k half)

    float c[4][4][4];
    #pragma unroll
    for (int mi = 0; mi < 4; mi++)
        #pragma unroll
        for (int ni = 0; ni < 4; ni++)
            #pragma unroll
            for (int r = 0; r < 4; r++) c[mi][ni][r] = 0.0f;

    auto load_stage = [&](int kt, int s) {
        uint32_t aT = tiles + s * STAGE_B;
        uint32_t bT = aT + TILE_B;
        const __half* As = Abase + kt * BK;
        const __half* Bs = Bbase + kt * BK;
        #pragma unroll
        for (int i = 0; i < 4; i++) {
            int idx = tid + i * 256;        // 0..1023
            int r = idx >> 3, ch = idx & 7; // row, 16B chunk
            uint32_t off = swz((uint32_t)(r * 128 + ch * 16));
            cp_async16(aT + off, As + (size_t)r * IN_F + ch * 8);
            cp_async16(bT + off, Bs + (size_t)r * IN_F + ch * 8);
        }
        cp_commit();
    };

    #pragma unroll
    for (int s = 0; s < STAGES; s++) load_stage(s, s);

    for (int kt = 0; kt < KT; kt++) {
        const int s = kt & 3;
        if      (kt < KT - 3)  cp_wait<3>();
        else if (kt == KT - 3) cp_wait<2>();
        else if (kt == KT - 2) cp_wait<1>();
        else                   cp_wait<0>();
        __syncthreads();

        const uint32_t sA = tiles + s * STAGE_B;
        const uint32_t sB = sA + TILE_B;

        #pragma unroll
        for (int kk = 0; kk < 4; kk++) {  // 4 x k16
            const uint32_t kb = kk * 32 + lm_h;
            uint32_t a[4][4];
            #pragma unroll
            for (int mi = 0; mi < 4; mi++) {
                uint32_t addr = sA + swz((uint32_t)((m_base + mi * 16 + lm_r) * 128) + kb);
                ldmatrix_x4(a[mi], addr);
            }
            uint32_t b[2][4];
            #pragma unroll
            for (int nb = 0; nb < 2; nb++) {
                uint32_t addr = sB + swz((uint32_t)((n_base + nb * 16 + lm_r) * 128) + kb);
                ldmatrix_x4(b[nb], addr);
            }
            #pragma unroll
            for (int mi = 0; mi < 4; mi++)
                #pragma unroll
                for (int ni = 0; ni < 4; ni++)
                    mma_f16(c[mi][ni], a[mi],
                            b[ni >> 1][ni & 1], b[ni >> 1][(ni & 1) + 2]);
        }
        __syncthreads();  // stage s fully consumed before it is refilled

        if (kt + 4 < KT) load_stage(kt + 4, s);
    }

    // epilogue: m16n8 C layout -> row = lane/4 (+8), col = (lane%4)*2 (+1)
    const int gid = lane >> 2;
    const int tig = lane & 3;
    #pragma unroll
    for (int mi = 0; mi < 4; mi++) {
        int row0 = bm * BM + m_base + mi * 16 + gid;
        #pragma unroll
        for (int ni = 0; ni < 4; ni++) {
            int col = bn * BN + n_base + ni * 8 + tig * 2;
            float b0 = __ldg(bias + col), b1 = __ldg(bias + col + 1);
            float2 v;
            v.x = c[mi][ni][0] + b0;
            v.y = c[mi][ni][1] + b1;
            *reinterpret_cast<float2*>(out + (size_t)row0 * OUT_F + col) = v;
            v.x = c[mi][ni][2] + b0;
            v.y = c[mi][ni][3] + b1;
            *reinterpret_cast<float2*>(out + (size_t)(row0 + 8) * OUT_F + col) = v;
        }
    }
}

// ----------------------------------------------------------------
extern "C" void kernel_launch(void* const* d_in, const int* in_sizes, int n_in,
                              void* d_out, int out_size) {
    const float* input   = (const float*)d_in[0];
    const int*   qweight = (const int*)  d_in[1];
    const float* scales  = (const float*)d_in[2];
    const float* zeros   = (const float*)d_in[3];
    const float* outlier = (const float*)d_in[4];
    const float* grad    = (const float*)d_in[5];
    const float* bias    = (const float*)d_in[6];
    float*       out     = (float*)d_out;

    cudaFuncSetAttribute(gemm_kernel, cudaFuncAttributeMaxDynamicSharedMemorySize, SMEM_SIZE);

    dequant_kernel<<<(OUT_F * IN_F / 4) / 256, 256>>>(qweight, scales, zeros, outlier, grad);
    xcvt_kernel<<<((size_t)M_ROWS * IN_F / 4) / 256, 256>>>(input);

    dim3 grid(M_ROWS / BM, OUT_F / BN);
    gemm_kernel<<<grid, 256, SMEM_SIZE>>>(bias, out);
}

// round 9
// speedup vs baseline: 2.0252x; 1.0796x over previous
#include <cuda_runtime.h>
#include <cuda_fp16.h>
#include <cstdint>

#define IN_F   4096
#define OUT_F  4096
#define M_ROWS 512

#define BM 128
#define BN 128
#define BK 64                  // fp16 elems -> 128B rows (XOR-swizzle atom)
#define KT (IN_F / BK)         // 64
#define STAGES 4
#define TILE_B  (BM * BK * 2)  // 16384 B per operand
#define STAGE_B (2 * TILE_B)   // 32 KB
#define SMEM_SIZE (STAGES * STAGE_B)  // 128 KB

#define W_BLOCKS ((OUT_F * IN_F / 4) / 256)            // 16384
#define X_BLOCKS (((M_ROWS) * IN_F / 4) / 256)         // 2048

// fp16 scratch: dequantized W [OUT_F][IN_F], converted X [M_ROWS][IN_F]
__device__ __half g_W[(size_t)OUT_F * IN_F];
__device__ __half g_X[(size_t)M_ROWS * IN_F];

// ---------------------------------------------------------------- helpers
__device__ __forceinline__ uint32_t s2u(const void* p) {
    uint32_t a;
    asm("{ .reg .u64 t; cvta.to.shared.u64 t, %1; cvt.u32.u64 %0, t; }" : "=r"(a) : "l"(p));
    return a;
}
__device__ __forceinline__ uint32_t swz(uint32_t b) { return b ^ ((b >> 3) & 0x70); }

__device__ __forceinline__ void cp_async16(uint32_t dst, const void* src) {
    asm volatile("cp.async.cg.shared.global [%0], [%1], 16;" :: "r"(dst), "l"(src));
}
__device__ __forceinline__ void cp_commit() { asm volatile("cp.async.commit_group;" ::: "memory"); }
template <int N> __device__ __forceinline__ void cp_wait() {
    asm volatile("cp.async.wait_group %0;" :: "n"(N) : "memory");
}

__device__ __forceinline__ void ldmatrix_x4(uint32_t* r, uint32_t addr) {
    asm volatile("ldmatrix.sync.aligned.m8n8.x4.shared.b16 {%0,%1,%2,%3}, [%4];"
                 : "=r"(r[0]), "=r"(r[1]), "=r"(r[2]), "=r"(r[3]) : "r"(addr));
}

__device__ __forceinline__ void mma_f16(float c[4], const uint32_t a[4],
                                        uint32_t b0, uint32_t b1) {
    asm volatile(
        "mma.sync.aligned.m16n8k16.row.col.f32.f16.f16.f32 "
        "{%0,%1,%2,%3}, {%4,%5,%6,%7}, {%8,%9}, {%0,%1,%2,%3};"
        : "+f"(c[0]), "+f"(c[1]), "+f"(c[2]), "+f"(c[3])
        : "r"(a[0]), "r"(a[1]), "r"(a[2]), "r"(a[3]), "r"(b0), "r"(b1));
}

__device__ __forceinline__ int4 ldcs_i4(const int* p) {
    int4 v;
    asm("ld.global.cs.v4.s32 {%0,%1,%2,%3}, [%4];"
        : "=r"(v.x), "=r"(v.y), "=r"(v.z), "=r"(v.w) : "l"(p));
    return v;
}
__device__ __forceinline__ float4 ldcs_f4(const float* p) {
    float4 v;
    asm("ld.global.cs.v4.f32 {%0,%1,%2,%3}, [%4];"
        : "=f"(v.x), "=f"(v.y), "=f"(v.z), "=f"(v.w) : "l"(p));
    return v;
}

// ---------------------------------------------------------------- pass 1: dequant W + convert X
__global__ void prep_kernel(const int* __restrict__ q,
                            const float* __restrict__ scales,
                            const float* __restrict__ zeros,
                            const float* __restrict__ outlier,
                            const float* __restrict__ grad,
                            const float* __restrict__ x) {
    int b = blockIdx.x;
    if (b < W_BLOCKS) {
        size_t base = ((size_t)b * blockDim.x + threadIdx.x) * 4;
        int row = (int)(base >> 12);  // IN_F = 4096
        float s = scales[row];
        float z = zeros[row];
        int4   qv = ldcs_i4(q + base);
        float4 ov = ldcs_f4(outlier + base);
        float4 gv = ldcs_f4(grad + base);
        float w0 = ((float)qv.x - z) * s + ov.x * gv.x;
        float w1 = ((float)qv.y - z) * s + ov.y * gv.y;
        float w2 = ((float)qv.z - z) * s + ov.z * gv.z;
        float w3 = ((float)qv.w - z) * s + ov.w * gv.w;
        union { __half2 h[2]; uint2 u; } cv;
        cv.h[0] = __floats2half2_rn(w0, w1);
        cv.h[1] = __floats2half2_rn(w2, w3);
        *reinterpret_cast<uint2*>(g_W + base) = cv.u;
    } else {
        size_t base = ((size_t)(b - W_BLOCKS) * blockDim.x + threadIdx.x) * 4;
        float4 v = *reinterpret_cast<const float4*>(x + base);
        union { __half2 h[2]; uint2 u; } cv;
        cv.h[0] = __floats2half2_rn(v.x, v.y);
        cv.h[1] = __floats2half2_rn(v.z, v.w);
        *reinterpret_cast<uint2*>(g_X + base) = cv.u;
    }
}

// ---------------------------------------------------------------- pass 2: fp16 mma.sync GEMM
// CTA 128x128, 8 warps (2x4), warp tile 64x32; single-sync 4-stage cp.async pipeline.
__global__ __launch_bounds__(256, 1)
void gemm_kernel(const float* __restrict__ bias, float* __restrict__ out) {
    extern __shared__ char smem_raw[];
    const uint32_t tiles = s2u(smem_raw);

    const int tid  = threadIdx.x;
    const int warp = tid >> 5;
    const int lane = tid & 31;
    const int bm   = blockIdx.x;  // 0..3 (fastest -> co-resident CTAs share W in L2)
    const int bn   = blockIdx.y;  // 0..31

    const int m_base = (warp & 1) * 64;   // 2 warps along M
    const int n_base = (warp >> 1) * 32;  // 4 warps along N

    const __half* Abase = g_X + (size_t)(bm * BM) * IN_F;
    const __half* Bbase = g_W + (size_t)(bn * BN) * IN_F;

    const int lm_r = lane & 15;        // row within 16
    const int lm_h = (lane >> 4) * 16; // k-half byte offset (0/16)

    float c[4][4][4];
    #pragma unroll
    for (int mi = 0; mi < 4; mi++)
        #pragma unroll
        for (int ni = 0; ni < 4; ni++)
            #pragma unroll
            for (int r = 0; r < 4; r++) c[mi][ni][r] = 0.0f;

    auto load_stage = [&](int kt, int s) {
        uint32_t aT = tiles + s * STAGE_B;
        uint32_t bT = aT + TILE_B;
        const __half* As = Abase + kt * BK;
        const __half* Bs = Bbase + kt * BK;
        #pragma unroll
        for (int i = 0; i < 4; i++) {
            int idx = tid + i * 256;        // 0..1023
            int r = idx >> 3, ch = idx & 7; // row, 16B chunk
            uint32_t off = swz((uint32_t)(r * 128 + ch * 16));
            cp_async16(aT + off, As + (size_t)r * IN_F + ch * 8);
            cp_async16(bT + off, Bs + (size_t)r * IN_F + ch * 8);
        }
        cp_commit();
    };

    // prologue: 3 stages in flight
    load_stage(0, 0);
    load_stage(1, 1);
    load_stage(2, 2);

    for (int kt = 0; kt < KT; kt++) {
        const int s = kt & 3;
        // stage kt ready when outstanding groups <= (#issued-ahead - 1)
        if      (kt <  KT - 2) cp_wait<2>();
        else if (kt == KT - 2) cp_wait<1>();
        else                   cp_wait<0>();
        __syncthreads();  // single barrier per iter: stage kt visible, stage kt-1 fully consumed

        // refill slot (kt+3)&3 == (kt-1)&3 — safe after the barrier above
        if (kt + 3 < KT) load_stage(kt + 3, (kt + 3) & 3);

        const uint32_t sA = tiles + s * STAGE_B;
        const uint32_t sB = sA + TILE_B;

        #pragma unroll
        for (int kk = 0; kk < 4; kk++) {  // 4 x k16
            const uint32_t kb = kk * 32 + lm_h;
            uint32_t a[4][4];
            #pragma unroll
            for (int mi = 0; mi < 4; mi++) {
                uint32_t addr = sA + swz((uint32_t)((m_base + mi * 16 + lm_r) * 128) + kb);
                ldmatrix_x4(a[mi], addr);
            }
            uint32_t b[2][4];
            #pragma unroll
            for (int nb = 0; nb < 2; nb++) {
                uint32_t addr = sB + swz((uint32_t)((n_base + nb * 16 + lm_r) * 128) + kb);
                ldmatrix_x4(b[nb], addr);
            }
            #pragma unroll
            for (int mi = 0; mi < 4; mi++)
                #pragma unroll
                for (int ni = 0; ni < 4; ni++)
                    mma_f16(c[mi][ni], a[mi],
                            b[ni >> 1][ni & 1], b[ni >> 1][(ni & 1) + 2]);
        }
    }

    // epilogue: m16n8 C layout -> row = lane/4 (+8), col = (lane%4)*2 (+1)
    const int gid = lane >> 2;
    const int tig = lane & 3;
    #pragma unroll
    for (int mi = 0; mi < 4; mi++) {
        int row0 = bm * BM + m_base + mi * 16 + gid;
        #pragma unroll
        for (int ni = 0; ni < 4; ni++) {
            int col = bn * BN + n_base + ni * 8 + tig * 2;
            float b0 = __ldg(bias + col), b1 = __ldg(bias + col + 1);
            float2 v;
            v.x = c[mi][ni][0] + b0;
            v.y = c[mi][ni][1] + b1;
            *reinterpret_cast<float2*>(out + (size_t)row0 * OUT_F + col) = v;
            v.x = c[mi][ni][2] + b0;
            v.y = c[mi][ni][3] + b1;
            *reinterpret_cast<float2*>(out + (size_t)(row0 + 8) * OUT_F + col) = v;
        }
    }
}

// ----------------------------------------------------------------
extern "C" void kernel_launch(void* const* d_in, const int* in_sizes, int n_in,
                              void* d_out, int out_size) {
    const float* input   = (const float*)d_in[0];
    const int*   qweight = (const int*)  d_in[1];
    const float* scales  = (const float*)d_in[2];
    const float* zeros   = (const float*)d_in[3];
    const float* outlier = (const float*)d_in[4];
    const float* grad    = (const float*)d_in[5];
    const float* bias    = (const float*)d_in[6];
    float*       out     = (float*)d_out;

    cudaFuncSetAttribute(gemm_kernel, cudaFuncAttributeMaxDynamicSharedMemorySize, SMEM_SIZE);

    prep_kernel<<<W_BLOCKS + X_BLOCKS, 256>>>(qweight, scales, zeros, outlier, grad, input);

    dim3 grid(M_ROWS / BM, OUT_F / BN);
    gemm_kernel<<<grid, 256, SMEM_SIZE>>>(bias, out);
}

// round 10
// speedup vs baseline: 2.0704x; 1.0223x over previous
#include <cuda_runtime.h>
#include <cuda_fp16.h>
#include <cstdint>

#define IN_F   4096
#define OUT_F  4096
#define M_ROWS 512

#define BM 128
#define BN 128
#define BK 64                  // fp16 elems -> 128B rows (XOR-swizzle atom)
#define KT (IN_F / BK)         // 64
#define STAGES 4
#define TILE_B  (BM * BK * 2)  // 16384 B per operand
#define STAGE_B (2 * TILE_B)   // 32 KB
#define SMEM_SIZE (STAGES * STAGE_B)  // 128 KB
#define NTHR 512               // 16 warps, 4x4 warp grid, warp tile 32x32

#define W_BLOCKS ((OUT_F * IN_F / 4) / 256)     // 16384
#define X_BLOCKS (((M_ROWS) * IN_F / 4) / 256)  // 2048

// fp16 scratch: dequantized W [OUT_F][IN_F], converted X [M_ROWS][IN_F]
__device__ __half g_W[(size_t)OUT_F * IN_F];
__device__ __half g_X[(size_t)M_ROWS * IN_F];

// ---------------------------------------------------------------- helpers
__device__ __forceinline__ uint32_t s2u(const void* p) {
    uint32_t a;
    asm("{ .reg .u64 t; cvta.to.shared.u64 t, %1; cvt.u32.u64 %0, t; }" : "=r"(a) : "l"(p));
    return a;
}
__device__ __forceinline__ uint32_t swz(uint32_t b) { return b ^ ((b >> 3) & 0x70); }

__device__ __forceinline__ void cp_async16(uint32_t dst, const void* src) {
    asm volatile("cp.async.cg.shared.global [%0], [%1], 16;" :: "r"(dst), "l"(src));
}
__device__ __forceinline__ void cp_commit() { asm volatile("cp.async.commit_group;" ::: "memory"); }
template <int N> __device__ __forceinline__ void cp_wait() {
    asm volatile("cp.async.wait_group %0;" :: "n"(N) : "memory");
}

__device__ __forceinline__ void ldmatrix_x4(uint32_t* r, uint32_t addr) {
    asm volatile("ldmatrix.sync.aligned.m8n8.x4.shared.b16 {%0,%1,%2,%3}, [%4];"
                 : "=r"(r[0]), "=r"(r[1]), "=r"(r[2]), "=r"(r[3]) : "r"(addr));
}

__device__ __forceinline__ void mma_f16(float c[4], const uint32_t a[4],
                                        uint32_t b0, uint32_t b1) {
    asm volatile(
        "mma.sync.aligned.m16n8k16.row.col.f32.f16.f16.f32 "
        "{%0,%1,%2,%3}, {%4,%5,%6,%7}, {%8,%9}, {%0,%1,%2,%3};"
        : "+f"(c[0]), "+f"(c[1]), "+f"(c[2]), "+f"(c[3])
        : "r"(a[0]), "r"(a[1]), "r"(a[2]), "r"(a[3]), "r"(b0), "r"(b1));
}

__device__ __forceinline__ int4 ldcs_i4(const int* p) {
    int4 v;
    asm("ld.global.cs.v4.s32 {%0,%1,%2,%3}, [%4];"
        : "=r"(v.x), "=r"(v.y), "=r"(v.z), "=r"(v.w) : "l"(p));
    return v;
}
__device__ __forceinline__ float4 ldcs_f4(const float* p) {
    float4 v;
    asm("ld.global.cs.v4.f32 {%0,%1,%2,%3}, [%4];"
        : "=f"(v.x), "=f"(v.y), "=f"(v.z), "=f"(v.w) : "l"(p));
    return v;
}

// ---------------------------------------------------------------- pass 1: dequant W + convert X
__global__ void prep_kernel(const int* __restrict__ q,
                            const float* __restrict__ scales,
                            const float* __restrict__ zeros,
                            const float* __restrict__ outlier,
                            const float* __restrict__ grad,
                            const float* __restrict__ x) {
    int b = blockIdx.x;
    if (b < W_BLOCKS) {
        size_t base = ((size_t)b * blockDim.x + threadIdx.x) * 4;
        int row = (int)(base >> 12);  // IN_F = 4096
        float s = scales[row];
        float z = zeros[row];
        int4   qv = ldcs_i4(q + base);
        float4 ov = ldcs_f4(outlier + base);
        float4 gv = ldcs_f4(grad + base);
        float w0 = ((float)qv.x - z) * s + ov.x * gv.x;
        float w1 = ((float)qv.y - z) * s + ov.y * gv.y;
        float w2 = ((float)qv.z - z) * s + ov.z * gv.z;
        float w3 = ((float)qv.w - z) * s + ov.w * gv.w;
        union { __half2 h[2]; uint2 u; } cv;
        cv.h[0] = __floats2half2_rn(w0, w1);
        cv.h[1] = __floats2half2_rn(w2, w3);
        *reinterpret_cast<uint2*>(g_W + base) = cv.u;
    } else {
        size_t base = ((size_t)(b - W_BLOCKS) * blockDim.x + threadIdx.x) * 4;
        float4 v = *reinterpret_cast<const float4*>(x + base);
        union { __half2 h[2]; uint2 u; } cv;
        cv.h[0] = __floats2half2_rn(v.x, v.y);
        cv.h[1] = __floats2half2_rn(v.z, v.w);
        *reinterpret_cast<uint2*>(g_X + base) = cv.u;
    }
}

// ---------------------------------------------------------------- pass 2: fp16 mma.sync GEMM
// CTA 128x128, 16 warps (4x4), warp tile 32x32; single-sync 4-stage cp.async pipeline.
__global__ __launch_bounds__(NTHR, 1)
void gemm_kernel(const float* __restrict__ bias, float* __restrict__ out) {
    extern __shared__ char smem_raw[];
    const uint32_t tiles = s2u(smem_raw);

    const int tid  = threadIdx.x;
    const int warp = tid >> 5;
    const int lane = tid & 31;
    const int bm   = blockIdx.x;  // 0..3 (fastest -> co-resident CTAs share W in L2)
    const int bn   = blockIdx.y;  // 0..31

    const int m_base = (warp & 3) * 32;   // 4 warps along M
    const int n_base = (warp >> 2) * 32;  // 4 warps along N

    const __half* Abase = g_X + (size_t)(bm * BM) * IN_F;
    const __half* Bbase = g_W + (size_t)(bn * BN) * IN_F;

    const int lm_r = lane & 15;        // row within 16
    const int lm_h = (lane >> 4) * 16; // k-half byte offset (0/16)

    float c[2][4][4];
    #pragma unroll
    for (int mi = 0; mi < 2; mi++)
        #pragma unroll
        for (int ni = 0; ni < 4; ni++)
            #pragma unroll
            for (int r = 0; r < 4; r++) c[mi][ni][r] = 0.0f;

    auto load_stage = [&](int kt, int s) {
        uint32_t aT = tiles + s * STAGE_B;
        uint32_t bT = aT + TILE_B;
        const __half* As = Abase + kt * BK;
        const __half* Bs = Bbase + kt * BK;
        #pragma unroll
        for (int i = 0; i < 2; i++) {
            int idx = tid + i * NTHR;       // 0..1023
            int r = idx >> 3, ch = idx & 7; // row, 16B chunk
            uint32_t off = swz((uint32_t)(r * 128 + ch * 16));
            cp_async16(aT + off, As + (size_t)r * IN_F + ch * 8);
            cp_async16(bT + off, Bs + (size_t)r * IN_F + ch * 8);
        }
        cp_commit();
    };

    // prologue: 3 stages in flight
    load_stage(0, 0);
    load_stage(1, 1);
    load_stage(2, 2);

    for (int kt = 0; kt < KT; kt++) {
        const int s = kt & 3;
        if      (kt <  KT - 2) cp_wait<2>();
        else if (kt == KT - 2) cp_wait<1>();
        else                   cp_wait<0>();
        __syncthreads();  // stage kt visible; stage kt-1 fully consumed

        if (kt + 3 < KT) load_stage(kt + 3, (kt + 3) & 3);

        const uint32_t sA = tiles + s * STAGE_B;
        const uint32_t sB = sA + TILE_B;

        #pragma unroll
        for (int kk = 0; kk < 4; kk++) {  // 4 x k16
            const uint32_t kb = kk * 32 + lm_h;
            uint32_t a[2][4];
            #pragma unroll
            for (int mi = 0; mi < 2; mi++) {
                uint32_t addr = sA + swz((uint32_t)((m_base + mi * 16 + lm_r) * 128) + kb);
                ldmatrix_x4(a[mi], addr);
            }
            uint32_t b[2][4];
            #pragma unroll
            for (int nb = 0; nb < 2; nb++) {
                uint32_t addr = sB + swz((uint32_t)((n_base + nb * 16 + lm_r) * 128) + kb);
                ldmatrix_x4(b[nb], addr);
            }
            #pragma unroll
            for (int mi = 0; mi < 2; mi++)
                #pragma unroll
                for (int ni = 0; ni < 4; ni++)
                    mma_f16(c[mi][ni], a[mi],
                            b[ni >> 1][ni & 1], b[ni >> 1][(ni & 1) + 2]);
        }
    }

    // epilogue: m16n8 C layout -> row = lane/4 (+8), col = (lane%4)*2 (+1)
    const int gid = lane >> 2;
    const int tig = lane & 3;
    #pragma unroll
    for (int mi = 0; mi < 2; mi++) {
        int row0 = bm * BM + m_base + mi * 16 + gid;
        #pragma unroll
        for (int ni = 0; ni < 4; ni++) {
            int col = bn * BN + n_base + ni * 8 + tig * 2;
            float b0 = __ldg(bias + col), b1 = __ldg(bias + col + 1);
            float2 v;
            v.x = c[mi][ni][0] + b0;
            v.y = c[mi][ni][1] + b1;
            *reinterpret_cast<float2*>(out + (size_t)row0 * OUT_F + col) = v;
            v.x = c[mi][ni][2] + b0;
            v.y = c[mi][ni][3] + b1;
            *reinterpret_cast<float2*>(out + (size_t)(row0 + 8) * OUT_F + col) = v;
        }
    }
}

// ----------------------------------------------------------------
extern "C" void kernel_launch(void* const* d_in, const int* in_sizes, int n_in,
                              void* d_out, int out_size) {
    const float* input   = (const float*)d_in[0];
    const int*   qweight = (const int*)  d_in[1];
    const float* scales  = (const float*)d_in[2];
    const float* zeros   = (const float*)d_in[3];
    const float* outlier = (const float*)d_in[4];
    const float* grad    = (const float*)d_in[5];
    const float* bias    = (const float*)d_in[6];
    float*       out     = (float*)d_out;

    cudaFuncSetAttribute(gemm_kernel, cudaFuncAttributeMaxDynamicSharedMemorySize, SMEM_SIZE);

    prep_kernel<<<W_BLOCKS + X_BLOCKS, 256>>>(qweight, scales, zeros, outlier, grad, input);

    dim3 grid(M_ROWS / BM, OUT_F / BN);
    gemm_kernel<<<grid, NTHR, SMEM_SIZE>>>(bias, out);
}